// round 11
// baseline (speedup 1.0000x reference)
#include <cuda_runtime.h>
#include <cuda_bf16.h>
#include <cstdint>

#define BB 8
#define SS 2048
#define DD 512
#define CC 1024
#define NROW (BB*SS)   // 16384

// ---------------------------------------------------------------------------
// Scratch (device globals), bf16 as ushort
// ---------------------------------------------------------------------------
__device__ unsigned short g_Xb[(size_t)NROW*DD], g_Yb[(size_t)NROW*DD];
__device__ unsigned short g_Wxqb[DD*DD], g_Wyqb[DD*DD];
__device__ unsigned short g_Wfkb[DD*CC], g_Wfvb[DD*CC];
__device__ unsigned short g_Qb[(size_t)NROW*CC];      // [row, 1024] = Q1|Q2
__device__ unsigned short g_Kb[(size_t)NROW*DD];
__device__ unsigned short g_Vtb[(size_t)BB*DD*SS];    // [b, d, s]
__device__ unsigned short g_Pb1[(size_t)BB*SS*SS];    // bf16 scores/probs (Q1)
__device__ unsigned short g_Pb2[(size_t)BB*SS*SS];    // bf16 scores/probs (Q2)

// ---------------------------------------------------------------------------
// Helpers
// ---------------------------------------------------------------------------
__device__ __forceinline__ uint32_t smem_u32(const void* p) {
    uint32_t a;
    asm("{ .reg .u64 t; cvta.to.shared.u64 t, %1; cvt.u32.u64 %0, t; }"
        : "=r"(a) : "l"(p));
    return a;
}
__device__ __forceinline__ void cp16(uint32_t s, const void* g) {
    asm volatile("cp.async.cg.shared.global [%0], [%1], 16;" :: "r"(s), "l"(g));
}
#define CP_COMMIT() asm volatile("cp.async.commit_group;" ::: "memory")
#define CP_WAIT1()  asm volatile("cp.async.wait_group 1;" ::: "memory")

__device__ __forceinline__ void ldm_x4(uint32_t* r, uint32_t a) {
    asm volatile("ldmatrix.sync.aligned.m8n8.x4.shared.b16 {%0,%1,%2,%3}, [%4];"
        : "=r"(r[0]), "=r"(r[1]), "=r"(r[2]), "=r"(r[3]) : "r"(a));
}
__device__ __forceinline__ void mma_bf16(float* d, const uint32_t* a, const uint32_t* b) {
    asm volatile(
        "mma.sync.aligned.m16n8k16.row.col.f32.bf16.bf16.f32 "
        "{%0,%1,%2,%3}, {%4,%5,%6,%7}, {%8,%9}, {%0,%1,%2,%3};"
        : "+f"(d[0]), "+f"(d[1]), "+f"(d[2]), "+f"(d[3])
        : "r"(a[0]), "r"(a[1]), "r"(a[2]), "r"(a[3]), "r"(b[0]), "r"(b[1]));
}
__device__ __forceinline__ unsigned short f2b(float v) {
    return __bfloat16_as_ushort(__float2bfloat16(v));
}
__device__ __forceinline__ float b2f(unsigned short v) {
    return __bfloat162float(__ushort_as_bfloat16(v));
}

// ---------------------------------------------------------------------------
// SMEM: STAGES x (A 128x64 | B 128x64) bf16, row stride 144B (conflict-free).
// 108KB per CTA -> two CTAs co-resident per SM (221KB <= 228KB).
// ---------------------------------------------------------------------------
#define STAGES     3
#define ROWB       144
#define A_TILE_B   (128 * ROWB)               // 18432
#define B_TILE_B   (128 * ROWB)               // 18432
#define STAGE_B    (A_TILE_B + B_TILE_B)      // 36864
#define SMEM_TOTAL (STAGES * STAGE_B)         // 110592

// ---------------------------------------------------------------------------
// Single-pass bf16 TN GEMM, CTA tile 128(m) x 128(n), 128 thr (4 warps,
// warp tile 64x64 -> LDSM duplication 2x/2x, 32 indep MMA per 8 LDSM),
// k-chunk 64, 2 CTAs/SM.
//
// z-split: if (blockIdx.z >= zsplit > 0) switch to the alt operand/output set.
// K-concat: A covers K via [Aseg1 (KA cols) | Aseg2]; B k-index wraps by bmask.
//
// mode 1: Cb[m*ld+n] = bf16(acc + bias[n])
// mode 2: Cb[n*ld+m] = bf16(acc + bias[n])   (transposed)
// mode 3: Cf[m*ld+n] = acc + add1? + add2?
// mode 5: Cb[m*ld+n] = bf16(alpha*acc)
// ---------------------------------------------------------------------------
__global__ __launch_bounds__(128, 2) void hmma_tn(
    const unsigned short* __restrict__ A, const unsigned short* __restrict__ Aseg2,
    int KA, const unsigned short* __restrict__ B, int bmask,
    int K, int lda, int ldb, long long a_bs, long long b_bs,
    int zsplit,
    int mode, float alpha, const float* __restrict__ bias,
    float* __restrict__ Cf, unsigned short* __restrict__ Cb,
    long long c_bs, int c_ld,
    const float* __restrict__ add1, const float* __restrict__ add2,
    const unsigned short* __restrict__ A_alt, const unsigned short* __restrict__ B_alt,
    const float* __restrict__ bias_alt, unsigned short* __restrict__ Cb_alt,
    long long cbs_alt, int cld_alt, int mode_alt)
{
    extern __shared__ char smem[];
    const uint32_t sbase = smem_u32(smem);

    const int tid  = threadIdx.x;
    const int wid  = tid >> 5;
    const int lane = tid & 31;
    const int warpM = wid >> 1;      // 0..1 (64 rows each)
    const int warpN = wid & 1;       // 0..1 (64 cols each)
    int bz = blockIdx.z;
    const int bm = blockIdx.y * 128, bn = blockIdx.x * 128;

    // operand-set select
    const unsigned short* Ab = A;
    const unsigned short* Bb = B;
    const float* biasp = bias;
    unsigned short* Cbp = Cb;
    long long cbs = c_bs;
    int cld = c_ld;
    int md = mode;
    if (zsplit > 0 && bz >= zsplit) {
        bz -= zsplit;
        Ab = A_alt; Bb = B_alt; biasp = bias_alt;
        Cbp = Cb_alt; cbs = cbs_alt; cld = cld_alt; md = mode_alt;
    }

    const unsigned short* gA1 = Ab + bz * a_bs + (long long)bm * lda;
    const unsigned short* gA2 =
        Aseg2 ? Aseg2 + bz * a_bs + (long long)bm * lda : nullptr;
    const unsigned short* gB = Bb + bz * b_bs + (long long)bn * ldb;

    float acc[4][8][4];
#pragma unroll
    for (int i = 0; i < 4; ++i)
#pragma unroll
        for (int j = 0; j < 8; ++j)
#pragma unroll
            for (int k = 0; k < 4; ++k) acc[i][j][k] = 0.f;

    const int nch = K >> 6;   // k-chunks of 64

    const int lr = tid >> 3, lc = tid & 7;   // 16 rows x 8 segs per pass
#define LOAD_CHUNK(c)                                                        \
    do {                                                                     \
        const int koff_ = (c) * 64;                                          \
        const unsigned short* gAc_ = gA1; int ka_ = koff_;                   \
        if (gA2 && koff_ >= KA) { gAc_ = gA2; ka_ = koff_ - KA; }            \
        const int kb_ = koff_ & bmask;                                       \
        const uint32_t sb_ = sbase + ((c) % STAGES) * STAGE_B;               \
        _Pragma("unroll")                                                    \
        for (int h_ = 0; h_ < 8; ++h_) {      /* A: 128 rows */              \
            const int row_ = lr + h_ * 16;                                   \
            cp16(sb_ + (uint32_t)(row_ * ROWB + lc * 16),                    \
                 gAc_ + (long long)row_ * lda + ka_ + lc * 8);               \
        }                                                                    \
        _Pragma("unroll")                                                    \
        for (int h_ = 0; h_ < 8; ++h_) {      /* B: 128 rows */              \
            const int row_ = lr + h_ * 16;                                   \
            cp16(sb_ + A_TILE_B + (uint32_t)(row_ * ROWB + lc * 16),         \
                 gB + (long long)row_ * ldb + kb_ + lc * 8);                 \
        }                                                                    \
        CP_COMMIT();                                                         \
    } while (0)

#pragma unroll
    for (int s = 0; s < STAGES - 1; ++s) LOAD_CHUNK(s);

    // ldmatrix geometry
    const int a_row = warpM * 64 + (lane & 15);
    const int a_colb = (lane >> 4) * 16;
    const int b_row = warpN * 64 + (lane & 7) + ((lane >> 4) & 1) * 8;
    const int b_colb = ((lane >> 3) & 1) * 16;

    for (int c = 0; c < nch; ++c) {
        CP_WAIT1();
        __syncthreads();

        // Issue next chunk's loads first: buffer (c+2)%3 was last read at
        // iter c-1; the barrier above ordered those reads before these writes.
        if (c + STAGES - 1 < nch) LOAD_CHUNK(c + STAGES - 1);
        else CP_COMMIT();   // one group per iteration for wait accounting

        const uint32_t tA = sbase + (c % STAGES) * STAGE_B;
        const uint32_t tB = tA + A_TILE_B;

#pragma unroll
        for (int ks = 0; ks < 4; ++ks) {      // four k16 steps per chunk
            uint32_t af[4][4], bfr[8][2];
#pragma unroll
            for (int mi = 0; mi < 4; ++mi)
                ldm_x4(af[mi], tA + (uint32_t)((a_row + mi * 16) * ROWB
                                               + ks * 32 + a_colb));
#pragma unroll
            for (int p = 0; p < 4; ++p) {     // n16 pair -> two n8 frags
                uint32_t r[4];
                ldm_x4(r, tB + (uint32_t)((b_row + p * 16) * ROWB
                                          + ks * 32 + b_colb));
                bfr[2*p][0] = r[0]; bfr[2*p][1] = r[1];
                bfr[2*p+1][0] = r[2]; bfr[2*p+1][1] = r[3];
            }
#pragma unroll
            for (int mi = 0; mi < 4; ++mi)
#pragma unroll
                for (int ni = 0; ni < 8; ++ni)
                    mma_bf16(acc[mi][ni], af[mi], bfr[ni]);
        }
    }
#undef LOAD_CHUNK

    // ------------------------- epilogue (register direct) -------------------
    const int g = lane >> 2, tig = lane & 3;
    const long long c_off = (long long)bz * cbs;

#pragma unroll
    for (int mi = 0; mi < 4; ++mi) {
#pragma unroll
        for (int ni = 0; ni < 8; ++ni) {
            const float* a = acc[mi][ni];
            const int m0 = bm + warpM * 64 + mi * 16 + g;
            const int n0 = bn + warpN * 64 + ni * 8 + tig * 2;
#pragma unroll
            for (int half = 0; half < 2; ++half) {
                const int m = m0 + half * 8;
                float v0 = a[half * 2 + 0];
                float v1 = a[half * 2 + 1];
                if (md == 5) {
                    *(ushort2*)&Cbp[c_off + (long long)m * cld + n0] =
                        make_ushort2(f2b(alpha * v0), f2b(alpha * v1));
                } else if (md == 1) {
                    v0 += __ldg(biasp + n0);
                    v1 += __ldg(biasp + n0 + 1);
                    *(ushort2*)&Cbp[c_off + (long long)m * cld + n0] =
                        make_ushort2(f2b(v0), f2b(v1));
                } else if (md == 2) {
                    v0 += __ldg(biasp + n0);
                    v1 += __ldg(biasp + n0 + 1);
                    Cbp[c_off + (long long)n0 * cld + m] = f2b(v0);
                    Cbp[c_off + (long long)(n0 + 1) * cld + m] = f2b(v1);
                } else {  // mode 3
                    const long long o = c_off + (long long)m * cld + n0;
                    if (add1) { float2 t = *(const float2*)&add1[o]; v0 += t.x; v1 += t.y; }
                    if (add2) { float2 t = *(const float2*)&add2[o]; v0 += t.x; v1 += t.y; }
                    *(float2*)&Cf[o] = make_float2(v0, v1);
                }
            }
        }
    }
}

// ---------------------------------------------------------------------------
// fp32 -> bf16: two equal-size arrays in one launch
// ---------------------------------------------------------------------------
__global__ __launch_bounds__(256) void tobf16_dual(
    const float* __restrict__ s1, unsigned short* __restrict__ d1,
    const float* __restrict__ s2, unsigned short* __restrict__ d2, int n)
{
    const int i = blockIdx.x * 256 + threadIdx.x;
    if (i < n) d1[i] = f2b(s1[i]);
    else if (i < 2 * n) d2[i - n] = f2b(s2[i - n]);
}

// ---------------------------------------------------------------------------
// Row softmax (rows of 2048) in place over two buffers in one launch
// ---------------------------------------------------------------------------
__global__ __launch_bounds__(256) void softmax_bf16(
    unsigned short* __restrict__ P1, unsigned short* __restrict__ P2)
{
    unsigned short* Pb = (blockIdx.x < NROW) ? P1 : P2;
    const long long rb = (long long)(blockIdx.x & (NROW - 1)) * 2048;
    const int t = threadIdx.x;
    __shared__ float red[8];

    float v[8];
    float mx = -3.0e38f;
#pragma unroll
    for (int i = 0; i < 8; ++i) {
        v[i] = b2f(Pb[rb + i * 256 + t]);
        mx = fmaxf(mx, v[i]);
    }
#pragma unroll
    for (int o = 16; o > 0; o >>= 1) mx = fmaxf(mx, __shfl_xor_sync(0xffffffffu, mx, o));
    if ((t & 31) == 0) red[t >> 5] = mx;
    __syncthreads();
    mx = red[0];
#pragma unroll
    for (int w = 1; w < 8; ++w) mx = fmaxf(mx, red[w]);
    __syncthreads();

    float s = 0.f;
#pragma unroll
    for (int i = 0; i < 8; ++i) {
        v[i] = __expf(v[i] - mx);
        s += v[i];
    }
#pragma unroll
    for (int o = 16; o > 0; o >>= 1) s += __shfl_xor_sync(0xffffffffu, s, o);
    if ((t & 31) == 0) red[t >> 5] = s;
    __syncthreads();
    s = red[0];
#pragma unroll
    for (int w = 1; w < 8; ++w) s += red[w];

    const float inv = 1.0f / s;
#pragma unroll
    for (int i = 0; i < 8; ++i) Pb[rb + i * 256 + t] = f2b(v[i] * inv);
}

// ---------------------------------------------------------------------------
// Launch sequence
// ---------------------------------------------------------------------------
extern "C" void kernel_launch(void* const* d_in, const int* in_sizes, int n_in,
                              void* d_out, int out_size)
{
    (void)in_sizes; (void)n_in; (void)out_size;

    const float* X    = (const float*)d_in[0];
    const float* Y    = (const float*)d_in[1];
    const float* W_xq = (const float*)d_in[2];
    const float* b_xq = (const float*)d_in[3];
    const float* W_yq = (const float*)d_in[4];
    const float* b_yq = (const float*)d_in[5];
    const float* W_fk = (const float*)d_in[6];
    const float* b_fk = (const float*)d_in[7];
    const float* W_fv = (const float*)d_in[8];
    const float* b_fv = (const float*)d_in[9];
    float* out = (float*)d_out;

#define SYM(T, name, gsym) T* name; cudaGetSymbolAddress((void**)&name, gsym)
    SYM(unsigned short, Xb, g_Xb);     SYM(unsigned short, Yb, g_Yb);
    SYM(unsigned short, Wxqb, g_Wxqb); SYM(unsigned short, Wyqb, g_Wyqb);
    SYM(unsigned short, Wfkb, g_Wfkb); SYM(unsigned short, Wfvb, g_Wfvb);
    SYM(unsigned short, Qb, g_Qb);     SYM(unsigned short, Kb, g_Kb);
    SYM(unsigned short, Vtb, g_Vtb);
    SYM(unsigned short, Pb1, g_Pb1);   SYM(unsigned short, Pb2, g_Pb2);
#undef SYM

    cudaFuncSetAttribute(hmma_tn, cudaFuncAttributeMaxDynamicSharedMemorySize, SMEM_TOTAL);

    const float scale = 0.04419417382415922f;  // 1/sqrt(512)
    const long long XBS = (long long)SS * DD;
    const long long QBS = (long long)SS * CC;
    const long long PBS = (long long)SS * SS;
    const long long VBS = (long long)DD * SS;

    // ---- bf16 conversions ----
    const int nX = NROW * DD;
    tobf16_dual<<<(2 * nX) / 256, 256>>>(X, Xb, Y, Yb, nX);
    tobf16_dual<<<(2 * DD * DD) / 256, 256>>>(W_xq, Wxqb, W_yq, Wyqb, DD * DD);
    tobf16_dual<<<(2 * DD * CC) / 256, 256>>>(W_fk, Wfkb, W_fv, Wfvb, DD * CC);

    // ---- projections: Q1 (z<8) and Q2 (z>=8) in one launch ----
    hmma_tn<<<dim3(4, 16, 16), 128, SMEM_TOTAL>>>(
        Xb, nullptr, DD, Wxqb, DD - 1,
        DD, DD, DD, XBS, 0, /*zsplit*/8,
        1, 1.f, b_xq, nullptr, Qb, QBS, CC, nullptr, nullptr,
        Yb, Wyqb, b_yq, Qb + DD, QBS, CC, 1);

    // ---- Kf (z<8, mode 1) and Vt (z>=8, mode 2 transposed) ----
    hmma_tn<<<dim3(4, 16, 16), 128, SMEM_TOTAL>>>(
        Qb, nullptr, CC, Wfkb, CC - 1,
        CC, CC, CC, QBS, 0, /*zsplit*/8,
        1, 1.f, b_fk, nullptr, Kb, XBS, DD, nullptr, nullptr,
        Qb, Wfvb, b_fv, Vtb, VBS, SS, 2);

    // ---- QK: scores for Q1 -> Pb1 (z<8) and Q2 -> Pb2 (z>=8) ----
    hmma_tn<<<dim3(16, 16, 16), 128, SMEM_TOTAL>>>(
        Qb, nullptr, DD, Kb, DD - 1,
        DD, CC, DD, QBS, XBS, /*zsplit*/8,
        5, scale, nullptr, nullptr, Pb1, PBS, SS, nullptr, nullptr,
        Qb + DD, Kb, nullptr, Pb2, PBS, SS, 5);

    // ---- softmax over both buffers ----
    softmax_bf16<<<2 * NROW, 256>>>(Pb1, Pb2);

    // ---- fused PV: out = P1@Vt^T + P2@Vt^T + X + Y  (K = 4096 concat) ----
    hmma_tn<<<dim3(4, 16, 8), 128, SMEM_TOTAL>>>(
        Pb1, Pb2, SS, Vtb, SS - 1,
        2 * SS, SS, SS, PBS, VBS, /*zsplit*/0,
        3, 1.f, nullptr, out, nullptr, XBS, DD, X, Y,
        nullptr, nullptr, nullptr, nullptr, 0, 0, 0);
}

// round 12
// speedup vs baseline: 1.1048x; 1.1048x over previous
#include <cuda_runtime.h>
#include <cuda_fp16.h>
#include <cstdint>

#define BB 8
#define SS 2048
#define DD 512
#define CC 1024
#define NROW (BB*SS)   // 16384

// ---------------------------------------------------------------------------
// Scratch (device globals), fp16 as ushort
// ---------------------------------------------------------------------------
__device__ unsigned short g_Xb[(size_t)NROW*DD], g_Yb[(size_t)NROW*DD];
__device__ unsigned short g_Wxqb[DD*DD], g_Wyqb[DD*DD];
__device__ unsigned short g_Wfkb[DD*CC], g_Wfvb[DD*CC];
__device__ unsigned short g_Qb[(size_t)NROW*CC];      // [row, 1024] = Q1|Q2
__device__ unsigned short g_Kb[(size_t)NROW*DD];
__device__ unsigned short g_Vtb[(size_t)BB*DD*SS];    // [b, d, s]
__device__ unsigned short g_Pb1[(size_t)BB*SS*SS];    // fp16 scores/probs (Q1)
__device__ unsigned short g_Pb2[(size_t)BB*SS*SS];    // fp16 scores/probs (Q2)

// ---------------------------------------------------------------------------
// Helpers
// ---------------------------------------------------------------------------
__device__ __forceinline__ uint32_t smem_u32(const void* p) {
    uint32_t a;
    asm("{ .reg .u64 t; cvta.to.shared.u64 t, %1; cvt.u32.u64 %0, t; }"
        : "=r"(a) : "l"(p));
    return a;
}
__device__ __forceinline__ void cp16(uint32_t s, const void* g) {
    asm volatile("cp.async.cg.shared.global [%0], [%1], 16;" :: "r"(s), "l"(g));
}
#define CP_COMMIT() asm volatile("cp.async.commit_group;" ::: "memory")
#define CP_WAIT1()  asm volatile("cp.async.wait_group 1;" ::: "memory")

__device__ __forceinline__ void ldm_x4(uint32_t* r, uint32_t a) {
    asm volatile("ldmatrix.sync.aligned.m8n8.x4.shared.b16 {%0,%1,%2,%3}, [%4];"
        : "=r"(r[0]), "=r"(r[1]), "=r"(r[2]), "=r"(r[3]) : "r"(a));
}
// fp16 MMA with fp16 accumulator: 2 acc regs (4 halves)
__device__ __forceinline__ void mma_f16(uint32_t* d, const uint32_t* a, const uint32_t* b) {
    asm volatile(
        "mma.sync.aligned.m16n8k16.row.col.f16.f16.f16.f16 "
        "{%0,%1}, {%2,%3,%4,%5}, {%6,%7}, {%0,%1};"
        : "+r"(d[0]), "+r"(d[1])
        : "r"(a[0]), "r"(a[1]), "r"(a[2]), "r"(a[3]), "r"(b[0]), "r"(b[1]));
}
__device__ __forceinline__ unsigned short f2h(float v) {
    return __half_as_ushort(__float2half_rn(v));
}
__device__ __forceinline__ float h2f(unsigned short v) {
    return __half2float(__ushort_as_half(v));
}

// ---------------------------------------------------------------------------
// SMEM: STAGES x (A 128x64 | B 128x64) fp16, row stride 144B (conflict-free).
// 108KB per CTA -> two CTAs co-resident per SM.
// ---------------------------------------------------------------------------
#define STAGES     3
#define ROWB       144
#define A_TILE_B   (128 * ROWB)               // 18432
#define B_TILE_B   (128 * ROWB)               // 18432
#define STAGE_B    (A_TILE_B + B_TILE_B)      // 36864
#define SMEM_TOTAL (STAGES * STAGE_B)         // 110592

// ---------------------------------------------------------------------------
// Single-pass fp16 TN GEMM (fp16 accumulate), CTA tile 128x128, 256 thr
// (8 warps, warp tile 64x32), k-chunk 64, 2 CTAs/SM.
//
// z-split: if (blockIdx.z >= zsplit > 0) switch to the alt operand/output set.
// K-concat: A covers K via [Aseg1 (KA cols) | Aseg2]; B k-index wraps by bmask.
//
// mode 1: Ch[m*ld+n] = f16(acc + bias[n])
// mode 2: Ch[n*ld+m] = f16(acc + bias[n])   (transposed)
// mode 3: Cf[m*ld+n] = acc + add1? + add2?
// mode 5: Ch[m*ld+n] = f16(alpha*acc)
// ---------------------------------------------------------------------------
__global__ __launch_bounds__(256, 2) void hmma_tn(
    const unsigned short* __restrict__ A, const unsigned short* __restrict__ Aseg2,
    int KA, const unsigned short* __restrict__ B, int bmask,
    int K, int lda, int ldb, long long a_bs, long long b_bs,
    int zsplit,
    int mode, float alpha, const float* __restrict__ bias,
    float* __restrict__ Cf, unsigned short* __restrict__ Cb,
    long long c_bs, int c_ld,
    const float* __restrict__ add1, const float* __restrict__ add2,
    const unsigned short* __restrict__ A_alt, const unsigned short* __restrict__ B_alt,
    const float* __restrict__ bias_alt, unsigned short* __restrict__ Cb_alt,
    long long cbs_alt, int cld_alt, int mode_alt)
{
    extern __shared__ char smem[];
    const uint32_t sbase = smem_u32(smem);

    const int tid  = threadIdx.x;
    const int wid  = tid >> 5;
    const int lane = tid & 31;
    const int warpM = wid >> 2;      // 0..1 (64 rows each)
    const int warpN = wid & 3;       // 0..3 (32 cols each)
    int bz = blockIdx.z;
    const int bm = blockIdx.y * 128, bn = blockIdx.x * 128;

    // operand-set select
    const unsigned short* Ab = A;
    const unsigned short* Bb = B;
    const float* biasp = bias;
    unsigned short* Cbp = Cb;
    long long cbs = c_bs;
    int cld = c_ld;
    int md = mode;
    if (zsplit > 0 && bz >= zsplit) {
        bz -= zsplit;
        Ab = A_alt; Bb = B_alt; biasp = bias_alt;
        Cbp = Cb_alt; cbs = cbs_alt; cld = cld_alt; md = mode_alt;
    }

    const unsigned short* gA1 = Ab + bz * a_bs + (long long)bm * lda;
    const unsigned short* gA2 =
        Aseg2 ? Aseg2 + bz * a_bs + (long long)bm * lda : nullptr;
    const unsigned short* gB = Bb + bz * b_bs + (long long)bn * ldb;

    uint32_t acc[4][4][2];
#pragma unroll
    for (int i = 0; i < 4; ++i)
#pragma unroll
        for (int j = 0; j < 4; ++j) { acc[i][j][0] = 0u; acc[i][j][1] = 0u; }

    const int nch = K >> 6;   // k-chunks of 64

    const int lr = tid >> 3, lc = tid & 7;   // 32 rows x 8 segs per pass
#define LOAD_CHUNK(c)                                                        \
    do {                                                                     \
        const int koff_ = (c) * 64;                                          \
        const unsigned short* gAc_ = gA1; int ka_ = koff_;                   \
        if (gA2 && koff_ >= KA) { gAc_ = gA2; ka_ = koff_ - KA; }            \
        const int kb_ = koff_ & bmask;                                       \
        const uint32_t sb_ = sbase + ((c) % STAGES) * STAGE_B;               \
        _Pragma("unroll")                                                    \
        for (int h_ = 0; h_ < 4; ++h_) {      /* A: 128 rows */              \
            const int row_ = lr + h_ * 32;                                   \
            cp16(sb_ + (uint32_t)(row_ * ROWB + lc * 16),                    \
                 gAc_ + (long long)row_ * lda + ka_ + lc * 8);               \
        }                                                                    \
        _Pragma("unroll")                                                    \
        for (int h_ = 0; h_ < 4; ++h_) {      /* B: 128 rows */              \
            const int row_ = lr + h_ * 32;                                   \
            cp16(sb_ + A_TILE_B + (uint32_t)(row_ * ROWB + lc * 16),         \
                 gB + (long long)row_ * ldb + kb_ + lc * 8);                 \
        }                                                                    \
        CP_COMMIT();                                                         \
    } while (0)

#pragma unroll
    for (int s = 0; s < STAGES - 1; ++s) LOAD_CHUNK(s);

    // ldmatrix geometry
    const int a_row = warpM * 64 + (lane & 15);
    const int a_colb = (lane >> 4) * 16;
    const int b_row = warpN * 32 + (lane & 7) + ((lane >> 4) & 1) * 8;
    const int b_colb = ((lane >> 3) & 1) * 16;

    for (int c = 0; c < nch; ++c) {
        CP_WAIT1();
        __syncthreads();

        // Issue next chunk's loads first: buffer (c+2)%3 was last read at
        // iter c-1; the barrier above ordered those reads before these writes.
        if (c + STAGES - 1 < nch) LOAD_CHUNK(c + STAGES - 1);
        else CP_COMMIT();   // one group per iteration for wait accounting

        const uint32_t tA = sbase + (c % STAGES) * STAGE_B;
        const uint32_t tB = tA + A_TILE_B;

#pragma unroll
        for (int ks = 0; ks < 4; ++ks) {      // four k16 steps per chunk
            uint32_t af[4][4], bfr[4][2];
#pragma unroll
            for (int mi = 0; mi < 4; ++mi)
                ldm_x4(af[mi], tA + (uint32_t)((a_row + mi * 16) * ROWB
                                               + ks * 32 + a_colb));
#pragma unroll
            for (int p = 0; p < 2; ++p) {     // n16 pair -> two n8 frags
                uint32_t r[4];
                ldm_x4(r, tB + (uint32_t)((b_row + p * 16) * ROWB
                                          + ks * 32 + b_colb));
                bfr[2*p][0] = r[0]; bfr[2*p][1] = r[1];
                bfr[2*p+1][0] = r[2]; bfr[2*p+1][1] = r[3];
            }
#pragma unroll
            for (int mi = 0; mi < 4; ++mi)
#pragma unroll
                for (int ni = 0; ni < 4; ++ni)
                    mma_f16(acc[mi][ni], af[mi], bfr[ni]);
        }
    }
#undef LOAD_CHUNK

    // ------------------------- epilogue (register direct) -------------------
    const int g = lane >> 2, tig = lane & 3;
    const long long c_off = (long long)bz * cbs;

#pragma unroll
    for (int mi = 0; mi < 4; ++mi) {
#pragma unroll
        for (int ni = 0; ni < 4; ++ni) {
            const int m0 = bm + warpM * 64 + mi * 16 + g;
            const int n0 = bn + warpN * 32 + ni * 8 + tig * 2;
#pragma unroll
            for (int half = 0; half < 2; ++half) {
                const int m = m0 + half * 8;
                const __half2 hv = *(const __half2*)&acc[mi][ni][half];
                float v0 = __low2float(hv);
                float v1 = __high2float(hv);
                if (md == 5) {
                    *(ushort2*)&Cbp[c_off + (long long)m * cld + n0] =
                        make_ushort2(f2h(alpha * v0), f2h(alpha * v1));
                } else if (md == 1) {
                    v0 += __ldg(biasp + n0);
                    v1 += __ldg(biasp + n0 + 1);
                    *(ushort2*)&Cbp[c_off + (long long)m * cld + n0] =
                        make_ushort2(f2h(v0), f2h(v1));
                } else if (md == 2) {
                    v0 += __ldg(biasp + n0);
                    v1 += __ldg(biasp + n0 + 1);
                    Cbp[c_off + (long long)n0 * cld + m] = f2h(v0);
                    Cbp[c_off + (long long)(n0 + 1) * cld + m] = f2h(v1);
                } else {  // mode 3
                    const long long o = c_off + (long long)m * cld + n0;
                    if (add1) { float2 t = *(const float2*)&add1[o]; v0 += t.x; v1 += t.y; }
                    if (add2) { float2 t = *(const float2*)&add2[o]; v0 += t.x; v1 += t.y; }
                    *(float2*)&Cf[o] = make_float2(v0, v1);
                }
            }
        }
    }
}

// ---------------------------------------------------------------------------
// fp32 -> fp16: two equal-size arrays in one launch
// ---------------------------------------------------------------------------
__global__ __launch_bounds__(256) void tofp16_dual(
    const float* __restrict__ s1, unsigned short* __restrict__ d1,
    const float* __restrict__ s2, unsigned short* __restrict__ d2, int n)
{
    const int i = blockIdx.x * 256 + threadIdx.x;
    if (i < n) d1[i] = f2h(s1[i]);
    else if (i < 2 * n) d2[i - n] = f2h(s2[i - n]);
}

// ---------------------------------------------------------------------------
// Row softmax (rows of 2048) in place over two buffers in one launch
// ---------------------------------------------------------------------------
__global__ __launch_bounds__(256) void softmax_f16(
    unsigned short* __restrict__ P1, unsigned short* __restrict__ P2)
{
    unsigned short* Pb = (blockIdx.x < NROW) ? P1 : P2;
    const long long rb = (long long)(blockIdx.x & (NROW - 1)) * 2048;
    const int t = threadIdx.x;
    __shared__ float red[8];

    float v[8];
    float mx = -3.0e38f;
#pragma unroll
    for (int i = 0; i < 8; ++i) {
        v[i] = h2f(Pb[rb + i * 256 + t]);
        mx = fmaxf(mx, v[i]);
    }
#pragma unroll
    for (int o = 16; o > 0; o >>= 1) mx = fmaxf(mx, __shfl_xor_sync(0xffffffffu, mx, o));
    if ((t & 31) == 0) red[t >> 5] = mx;
    __syncthreads();
    mx = red[0];
#pragma unroll
    for (int w = 1; w < 8; ++w) mx = fmaxf(mx, red[w]);
    __syncthreads();

    float s = 0.f;
#pragma unroll
    for (int i = 0; i < 8; ++i) {
        v[i] = __expf(v[i] - mx);
        s += v[i];
    }
#pragma unroll
    for (int o = 16; o > 0; o >>= 1) s += __shfl_xor_sync(0xffffffffu, s, o);
    if ((t & 31) == 0) red[t >> 5] = s;
    __syncthreads();
    s = red[0];
#pragma unroll
    for (int w = 1; w < 8; ++w) s += red[w];

    const float inv = 1.0f / s;
#pragma unroll
    for (int i = 0; i < 8; ++i) Pb[rb + i * 256 + t] = f2h(v[i] * inv);
}

// ---------------------------------------------------------------------------
// Launch sequence
// ---------------------------------------------------------------------------
extern "C" void kernel_launch(void* const* d_in, const int* in_sizes, int n_in,
                              void* d_out, int out_size)
{
    (void)in_sizes; (void)n_in; (void)out_size;

    const float* X    = (const float*)d_in[0];
    const float* Y    = (const float*)d_in[1];
    const float* W_xq = (const float*)d_in[2];
    const float* b_xq = (const float*)d_in[3];
    const float* W_yq = (const float*)d_in[4];
    const float* b_yq = (const float*)d_in[5];
    const float* W_fk = (const float*)d_in[6];
    const float* b_fk = (const float*)d_in[7];
    const float* W_fv = (const float*)d_in[8];
    const float* b_fv = (const float*)d_in[9];
    float* out = (float*)d_out;

#define SYM(T, name, gsym) T* name; cudaGetSymbolAddress((void**)&name, gsym)
    SYM(unsigned short, Xb, g_Xb);     SYM(unsigned short, Yb, g_Yb);
    SYM(unsigned short, Wxqb, g_Wxqb); SYM(unsigned short, Wyqb, g_Wyqb);
    SYM(unsigned short, Wfkb, g_Wfkb); SYM(unsigned short, Wfvb, g_Wfvb);
    SYM(unsigned short, Qb, g_Qb);     SYM(unsigned short, Kb, g_Kb);
    SYM(unsigned short, Vtb, g_Vtb);
    SYM(unsigned short, Pb1, g_Pb1);   SYM(unsigned short, Pb2, g_Pb2);
#undef SYM

    cudaFuncSetAttribute(hmma_tn, cudaFuncAttributeMaxDynamicSharedMemorySize, SMEM_TOTAL);

    const float scale = 0.04419417382415922f;  // 1/sqrt(512)
    const long long XBS = (long long)SS * DD;
    const long long QBS = (long long)SS * CC;
    const long long PBS = (long long)SS * SS;
    const long long VBS = (long long)DD * SS;

    // ---- fp16 conversions ----
    const int nX = NROW * DD;
    tofp16_dual<<<(2 * nX) / 256, 256>>>(X, Xb, Y, Yb, nX);
    tofp16_dual<<<(2 * DD * DD) / 256, 256>>>(W_xq, Wxqb, W_yq, Wyqb, DD * DD);
    tofp16_dual<<<(2 * DD * CC) / 256, 256>>>(W_fk, Wfkb, W_fv, Wfvb, DD * CC);

    // ---- projections: Q1 (z<8) and Q2 (z>=8) in one launch ----
    hmma_tn<<<dim3(4, 16, 16), 256, SMEM_TOTAL>>>(
        Xb, nullptr, DD, Wxqb, DD - 1,
        DD, DD, DD, XBS, 0, /*zsplit*/8,
        1, 1.f, b_xq, nullptr, Qb, QBS, CC, nullptr, nullptr,
        Yb, Wyqb, b_yq, Qb + DD, QBS, CC, 1);

    // ---- Kf (z<8, mode 1) and Vt (z>=8, mode 2 transposed) ----
    hmma_tn<<<dim3(4, 16, 16), 256, SMEM_TOTAL>>>(
        Qb, nullptr, CC, Wfkb, CC - 1,
        CC, CC, CC, QBS, 0, /*zsplit*/8,
        1, 1.f, b_fk, nullptr, Kb, XBS, DD, nullptr, nullptr,
        Qb, Wfvb, b_fv, Vtb, VBS, SS, 2);

    // ---- QK: scores for Q1 -> Pb1 (z<8) and Q2 -> Pb2 (z>=8) ----
    hmma_tn<<<dim3(16, 16, 16), 256, SMEM_TOTAL>>>(
        Qb, nullptr, DD, Kb, DD - 1,
        DD, CC, DD, QBS, XBS, /*zsplit*/8,
        5, scale, nullptr, nullptr, Pb1, PBS, SS, nullptr, nullptr,
        Qb + DD, Kb, nullptr, Pb2, PBS, SS, 5);

    // ---- softmax over both buffers ----
    softmax_f16<<<2 * NROW, 256>>>(Pb1, Pb2);

    // ---- fused PV: out = P1@Vt^T + P2@Vt^T + X + Y  (K = 4096 concat) ----
    hmma_tn<<<dim3(4, 16, 8), 256, SMEM_TOTAL>>>(
        Pb1, Pb2, SS, Vtb, SS - 1,
        2 * SS, SS, SS, PBS, VBS, /*zsplit*/0,
        3, 1.f, nullptr, out, nullptr, XBS, DD, X, Y,
        nullptr, nullptr, nullptr, nullptr, 0, 0, 0);
}

// round 13
// speedup vs baseline: 1.1501x; 1.0409x over previous
#include <cuda_runtime.h>
#include <cuda_fp16.h>
#include <cstdint>

#define BB 8
#define SS 2048
#define DD 512
#define CC 1024
#define NROW (BB*SS)   // 16384

// ---------------------------------------------------------------------------
// Scratch (device globals), fp16 as ushort
// ---------------------------------------------------------------------------
__device__ unsigned short g_Xb[(size_t)NROW*DD], g_Yb[(size_t)NROW*DD];
__device__ unsigned short g_Wxqb[DD*DD], g_Wyqb[DD*DD];
__device__ unsigned short g_Wfkb[DD*CC], g_Wfvb[DD*CC];
__device__ unsigned short g_Qb[(size_t)NROW*CC];      // [row, 1024] = Q1|Q2
__device__ unsigned short g_Kb[(size_t)NROW*DD];
__device__ unsigned short g_Vtb[(size_t)BB*DD*SS];    // [b, d, s]
__device__ unsigned short g_Pb1[(size_t)BB*SS*SS];    // fp16 scores/probs (Q1)
__device__ unsigned short g_Pb2[(size_t)BB*SS*SS];    // fp16 scores/probs (Q2)

// ---------------------------------------------------------------------------
// Helpers
// ---------------------------------------------------------------------------
__device__ __forceinline__ uint32_t smem_u32(const void* p) {
    uint32_t a;
    asm("{ .reg .u64 t; cvta.to.shared.u64 t, %1; cvt.u32.u64 %0, t; }"
        : "=r"(a) : "l"(p));
    return a;
}
__device__ __forceinline__ void cp16(uint32_t s, const void* g) {
    asm volatile("cp.async.cg.shared.global [%0], [%1], 16;" :: "r"(s), "l"(g));
}
#define CP_COMMIT() asm volatile("cp.async.commit_group;" ::: "memory")
#define CP_WAIT0()  asm volatile("cp.async.wait_group 0;" ::: "memory")

__device__ __forceinline__ void ldm_x4(uint32_t* r, uint32_t a) {
    asm volatile("ldmatrix.sync.aligned.m8n8.x4.shared.b16 {%0,%1,%2,%3}, [%4];"
        : "=r"(r[0]), "=r"(r[1]), "=r"(r[2]), "=r"(r[3]) : "r"(a));
}
// fp16 MMA with fp16 accumulator: 2 acc regs (4 halves)
__device__ __forceinline__ void mma_f16(uint32_t* d, const uint32_t* a, const uint32_t* b) {
    asm volatile(
        "mma.sync.aligned.m16n8k16.row.col.f16.f16.f16.f16 "
        "{%0,%1}, {%2,%3,%4,%5}, {%6,%7}, {%0,%1};"
        : "+r"(d[0]), "+r"(d[1])
        : "r"(a[0]), "r"(a[1]), "r"(a[2]), "r"(a[3]), "r"(b[0]), "r"(b[1]));
}
__device__ __forceinline__ unsigned short f2h(float v) {
    return __half_as_ushort(__float2half_rn(v));
}
__device__ __forceinline__ float h2f(unsigned short v) {
    return __half2float(__ushort_as_half(v));
}

// ---------------------------------------------------------------------------
// SMEM: 2 stages x (A 128x64 | B 256x64) fp16, row stride 144B (conflict-free).
// 108KB per CTA -> two CTAs co-resident per SM.
// ---------------------------------------------------------------------------
#define STAGES     2
#define ROWB       144
#define A_TILE_B   (128 * ROWB)               // 18432
#define B_TILE_B   (256 * ROWB)               // 36864
#define STAGE_B    (A_TILE_B + B_TILE_B)      // 55296
#define SMEM_TOTAL (STAGES * STAGE_B)         // 110592

// ---------------------------------------------------------------------------
// Single-pass fp16 TN GEMM (fp16 acc), CTA tile 128(m) x 256(n), 256 thr
// (8 warps 2x4, warp tile 64x64 -> A dup x4, B dup x2: 182 B/MMA crossbar),
// k-chunk 64, double-buffered, 2 CTAs/SM.
//
// z-split: if (blockIdx.z >= zsplit > 0) switch to the alt operand/output set.
// K-concat: A covers K via [Aseg1 (KA cols) | Aseg2]; B k-index wraps by bmask.
//
// mode 1: Ch[m*ld+n] = f16(acc + bias[n])
// mode 2: Ch[n*ld+m] = f16(acc + bias[n])   (transposed)
// mode 3: Cf[m*ld+n] = acc + add1? + add2?
// mode 5: Ch[m*ld+n] = f16(alpha*acc)
// ---------------------------------------------------------------------------
__global__ __launch_bounds__(256, 2) void hmma_tn(
    const unsigned short* __restrict__ A, const unsigned short* __restrict__ Aseg2,
    int KA, const unsigned short* __restrict__ B, int bmask,
    int K, int lda, int ldb, long long a_bs, long long b_bs,
    int zsplit,
    int mode, float alpha, const float* __restrict__ bias,
    float* __restrict__ Cf, unsigned short* __restrict__ Cb,
    long long c_bs, int c_ld,
    const float* __restrict__ add1, const float* __restrict__ add2,
    const unsigned short* __restrict__ A_alt, const unsigned short* __restrict__ B_alt,
    const float* __restrict__ bias_alt, unsigned short* __restrict__ Cb_alt,
    long long cbs_alt, int cld_alt, int mode_alt)
{
    extern __shared__ char smem[];
    const uint32_t sbase = smem_u32(smem);

    const int tid  = threadIdx.x;
    const int wid  = tid >> 5;
    const int lane = tid & 31;
    const int warpM = wid >> 2;      // 0..1 (64 rows each)
    const int warpN = wid & 3;       // 0..3 (64 cols each)
    int bz = blockIdx.z;
    const int bm = blockIdx.y * 128, bn = blockIdx.x * 256;

    // operand-set select
    const unsigned short* Ab = A;
    const unsigned short* Bb = B;
    const float* biasp = bias;
    unsigned short* Cbp = Cb;
    long long cbs = c_bs;
    int cld = c_ld;
    int md = mode;
    if (zsplit > 0 && bz >= zsplit) {
        bz -= zsplit;
        Ab = A_alt; Bb = B_alt; biasp = bias_alt;
        Cbp = Cb_alt; cbs = cbs_alt; cld = cld_alt; md = mode_alt;
    }

    const unsigned short* gA1 = Ab + bz * a_bs + (long long)bm * lda;
    const unsigned short* gA2 =
        Aseg2 ? Aseg2 + bz * a_bs + (long long)bm * lda : nullptr;
    const unsigned short* gB = Bb + bz * b_bs + (long long)bn * ldb;

    uint32_t acc[4][8][2];
#pragma unroll
    for (int i = 0; i < 4; ++i)
#pragma unroll
        for (int j = 0; j < 8; ++j) { acc[i][j][0] = 0u; acc[i][j][1] = 0u; }

    const int nch = K >> 6;   // k-chunks of 64

    const int lr = tid >> 3, lc = tid & 7;   // 32 rows x 8 segs per pass
#define LOAD_CHUNK(c)                                                        \
    do {                                                                     \
        const int koff_ = (c) * 64;                                          \
        const unsigned short* gAc_ = gA1; int ka_ = koff_;                   \
        if (gA2 && koff_ >= KA) { gAc_ = gA2; ka_ = koff_ - KA; }            \
        const int kb_ = koff_ & bmask;                                       \
        const uint32_t sb_ = sbase + ((c) & 1) * STAGE_B;                    \
        _Pragma("unroll")                                                    \
        for (int h_ = 0; h_ < 4; ++h_) {      /* A: 128 rows */              \
            const int row_ = lr + h_ * 32;                                   \
            cp16(sb_ + (uint32_t)(row_ * ROWB + lc * 16),                    \
                 gAc_ + (long long)row_ * lda + ka_ + lc * 8);               \
        }                                                                    \
        _Pragma("unroll")                                                    \
        for (int h_ = 0; h_ < 8; ++h_) {      /* B: 256 rows */              \
            const int row_ = lr + h_ * 32;                                   \
            cp16(sb_ + A_TILE_B + (uint32_t)(row_ * ROWB + lc * 16),         \
                 gB + (long long)row_ * ldb + kb_ + lc * 8);                 \
        }                                                                    \
        CP_COMMIT();                                                         \
    } while (0)

    LOAD_CHUNK(0);

    // ldmatrix geometry
    const int a_row = warpM * 64 + (lane & 15);
    const int a_colb = (lane >> 4) * 16;
    const int b_row = warpN * 64 + (lane & 7) + ((lane >> 4) & 1) * 8;
    const int b_colb = ((lane >> 3) & 1) * 16;

    for (int c = 0; c < nch; ++c) {
        CP_WAIT0();            // chunk c resident
        __syncthreads();       // all warps done reading buffer (c&1) from c-2

        // Prefetch chunk c+1 into the other buffer; overlaps compute below.
        if (c + 1 < nch) LOAD_CHUNK(c + 1);

        const uint32_t tA = sbase + (c & 1) * STAGE_B;
        const uint32_t tB = tA + A_TILE_B;

#pragma unroll
        for (int ks = 0; ks < 4; ++ks) {      // four k16 steps per chunk
            uint32_t af[4][4], bfr[8][2];
#pragma unroll
            for (int mi = 0; mi < 4; ++mi)
                ldm_x4(af[mi], tA + (uint32_t)((a_row + mi * 16) * ROWB
                                               + ks * 32 + a_colb));
#pragma unroll
            for (int p = 0; p < 4; ++p) {     // n16 pair -> two n8 frags
                uint32_t r[4];
                ldm_x4(r, tB + (uint32_t)((b_row + p * 16) * ROWB
                                          + ks * 32 + b_colb));
                bfr[2*p][0] = r[0]; bfr[2*p][1] = r[1];
                bfr[2*p+1][0] = r[2]; bfr[2*p+1][1] = r[3];
            }
#pragma unroll
            for (int mi = 0; mi < 4; ++mi)
#pragma unroll
                for (int ni = 0; ni < 8; ++ni)
                    mma_f16(acc[mi][ni], af[mi], bfr[ni]);
        }
    }
#undef LOAD_CHUNK

    // ------------------------- epilogue (register direct) -------------------
    const int g = lane >> 2, tig = lane & 3;
    const long long c_off = (long long)bz * cbs;

#pragma unroll
    for (int mi = 0; mi < 4; ++mi) {
#pragma unroll
        for (int ni = 0; ni < 8; ++ni) {
            const int m0 = bm + warpM * 64 + mi * 16 + g;
            const int n0 = bn + warpN * 64 + ni * 8 + tig * 2;
#pragma unroll
            for (int half = 0; half < 2; ++half) {
                const int m = m0 + half * 8;
                const __half2 hv = *(const __half2*)&acc[mi][ni][half];
                float v0 = __low2float(hv);
                float v1 = __high2float(hv);
                if (md == 5) {
                    *(ushort2*)&Cbp[c_off + (long long)m * cld + n0] =
                        make_ushort2(f2h(alpha * v0), f2h(alpha * v1));
                } else if (md == 1) {
                    v0 += __ldg(biasp + n0);
                    v1 += __ldg(biasp + n0 + 1);
                    *(ushort2*)&Cbp[c_off + (long long)m * cld + n0] =
                        make_ushort2(f2h(v0), f2h(v1));
                } else if (md == 2) {
                    v0 += __ldg(biasp + n0);
                    v1 += __ldg(biasp + n0 + 1);
                    Cbp[c_off + (long long)n0 * cld + m] = f2h(v0);
                    Cbp[c_off + (long long)(n0 + 1) * cld + m] = f2h(v1);
                } else {  // mode 3
                    const long long o = c_off + (long long)m * cld + n0;
                    if (add1) { float2 t = *(const float2*)&add1[o]; v0 += t.x; v1 += t.y; }
                    if (add2) { float2 t = *(const float2*)&add2[o]; v0 += t.x; v1 += t.y; }
                    *(float2*)&Cf[o] = make_float2(v0, v1);
                }
            }
        }
    }
}

// ---------------------------------------------------------------------------
// fp32 -> fp16: two equal-size arrays in one launch
// ---------------------------------------------------------------------------
__global__ __launch_bounds__(256) void tofp16_dual(
    const float* __restrict__ s1, unsigned short* __restrict__ d1,
    const float* __restrict__ s2, unsigned short* __restrict__ d2, int n)
{
    const int i = blockIdx.x * 256 + threadIdx.x;
    if (i < n) d1[i] = f2h(s1[i]);
    else if (i < 2 * n) d2[i - n] = f2h(s2[i - n]);
}

// ---------------------------------------------------------------------------
// Row softmax (rows of 2048) in place over two buffers in one launch
// ---------------------------------------------------------------------------
__global__ __launch_bounds__(256) void softmax_f16(
    unsigned short* __restrict__ P1, unsigned short* __restrict__ P2)
{
    unsigned short* Pb = (blockIdx.x < NROW) ? P1 : P2;
    const long long rb = (long long)(blockIdx.x & (NROW - 1)) * 2048;
    const int t = threadIdx.x;
    __shared__ float red[8];

    float v[8];
    float mx = -3.0e38f;
#pragma unroll
    for (int i = 0; i < 8; ++i) {
        v[i] = h2f(Pb[rb + i * 256 + t]);
        mx = fmaxf(mx, v[i]);
    }
#pragma unroll
    for (int o = 16; o > 0; o >>= 1) mx = fmaxf(mx, __shfl_xor_sync(0xffffffffu, mx, o));
    if ((t & 31) == 0) red[t >> 5] = mx;
    __syncthreads();
    mx = red[0];
#pragma unroll
    for (int w = 1; w < 8; ++w) mx = fmaxf(mx, red[w]);
    __syncthreads();

    float s = 0.f;
#pragma unroll
    for (int i = 0; i < 8; ++i) {
        v[i] = __expf(v[i] - mx);
        s += v[i];
    }
#pragma unroll
    for (int o = 16; o > 0; o >>= 1) s += __shfl_xor_sync(0xffffffffu, s, o);
    if ((t & 31) == 0) red[t >> 5] = s;
    __syncthreads();
    s = red[0];
#pragma unroll
    for (int w = 1; w < 8; ++w) s += red[w];

    const float inv = 1.0f / s;
#pragma unroll
    for (int i = 0; i < 8; ++i) Pb[rb + i * 256 + t] = f2h(v[i] * inv);
}

// ---------------------------------------------------------------------------
// Launch sequence
// ---------------------------------------------------------------------------
extern "C" void kernel_launch(void* const* d_in, const int* in_sizes, int n_in,
                              void* d_out, int out_size)
{
    (void)in_sizes; (void)n_in; (void)out_size;

    const float* X    = (const float*)d_in[0];
    const float* Y    = (const float*)d_in[1];
    const float* W_xq = (const float*)d_in[2];
    const float* b_xq = (const float*)d_in[3];
    const float* W_yq = (const float*)d_in[4];
    const float* b_yq = (const float*)d_in[5];
    const float* W_fk = (const float*)d_in[6];
    const float* b_fk = (const float*)d_in[7];
    const float* W_fv = (const float*)d_in[8];
    const float* b_fv = (const float*)d_in[9];
    float* out = (float*)d_out;

#define SYM(T, name, gsym) T* name; cudaGetSymbolAddress((void**)&name, gsym)
    SYM(unsigned short, Xb, g_Xb);     SYM(unsigned short, Yb, g_Yb);
    SYM(unsigned short, Wxqb, g_Wxqb); SYM(unsigned short, Wyqb, g_Wyqb);
    SYM(unsigned short, Wfkb, g_Wfkb); SYM(unsigned short, Wfvb, g_Wfvb);
    SYM(unsigned short, Qb, g_Qb);     SYM(unsigned short, Kb, g_Kb);
    SYM(unsigned short, Vtb, g_Vtb);
    SYM(unsigned short, Pb1, g_Pb1);   SYM(unsigned short, Pb2, g_Pb2);
#undef SYM

    cudaFuncSetAttribute(hmma_tn, cudaFuncAttributeMaxDynamicSharedMemorySize, SMEM_TOTAL);

    const float scale = 0.04419417382415922f;  // 1/sqrt(512)
    const long long XBS = (long long)SS * DD;
    const long long QBS = (long long)SS * CC;
    const long long PBS = (long long)SS * SS;
    const long long VBS = (long long)DD * SS;

    // ---- fp16 conversions ----
    const int nX = NROW * DD;
    tofp16_dual<<<(2 * nX) / 256, 256>>>(X, Xb, Y, Yb, nX);
    tofp16_dual<<<(2 * DD * DD) / 256, 256>>>(W_xq, Wxqb, W_yq, Wyqb, DD * DD);
    tofp16_dual<<<(2 * DD * CC) / 256, 256>>>(W_fk, Wfkb, W_fv, Wfvb, DD * CC);

    // ---- projections: Q1 (z<8) and Q2 (z>=8) in one launch ----
    hmma_tn<<<dim3(2, 16, 16), 256, SMEM_TOTAL>>>(
        Xb, nullptr, DD, Wxqb, DD - 1,
        DD, DD, DD, XBS, 0, /*zsplit*/8,
        1, 1.f, b_xq, nullptr, Qb, QBS, CC, nullptr, nullptr,
        Yb, Wyqb, b_yq, Qb + DD, QBS, CC, 1);

    // ---- Kf (z<8, mode 1) and Vt (z>=8, mode 2 transposed) ----
    hmma_tn<<<dim3(2, 16, 16), 256, SMEM_TOTAL>>>(
        Qb, nullptr, CC, Wfkb, CC - 1,
        CC, CC, CC, QBS, 0, /*zsplit*/8,
        1, 1.f, b_fk, nullptr, Kb, XBS, DD, nullptr, nullptr,
        Qb, Wfvb, b_fv, Vtb, VBS, SS, 2);

    // ---- QK: scores for Q1 -> Pb1 (z<8) and Q2 -> Pb2 (z>=8) ----
    hmma_tn<<<dim3(8, 16, 16), 256, SMEM_TOTAL>>>(
        Qb, nullptr, DD, Kb, DD - 1,
        DD, CC, DD, QBS, XBS, /*zsplit*/8,
        5, scale, nullptr, nullptr, Pb1, PBS, SS, nullptr, nullptr,
        Qb + DD, Kb, nullptr, Pb2, PBS, SS, 5);

    // ---- softmax over both buffers ----
    softmax_f16<<<2 * NROW, 256>>>(Pb1, Pb2);

    // ---- fused PV: out = P1@Vt^T + P2@Vt^T + X + Y  (K = 4096 concat) ----
    hmma_tn<<<dim3(2, 16, 8), 256, SMEM_TOTAL>>>(
        Pb1, Pb2, SS, Vtb, SS - 1,
        2 * SS, SS, SS, PBS, VBS, /*zsplit*/0,
        3, 1.f, nullptr, out, nullptr, XBS, DD, X, Y,
        nullptr, nullptr, nullptr, nullptr, 0, 0, 0);
}

// round 14
// speedup vs baseline: 1.2068x; 1.0493x over previous
#include <cuda_runtime.h>
#include <cuda_fp16.h>
#include <cstdint>

#define BB 8
#define SS 2048
#define DD 512
#define CC 1024
#define NROW (BB*SS)   // 16384

// ---------------------------------------------------------------------------
// Scratch (device globals), fp16 as ushort
// ---------------------------------------------------------------------------
__device__ unsigned short g_Xb[(size_t)NROW*DD], g_Yb[(size_t)NROW*DD];
__device__ unsigned short g_Wxqb[DD*DD], g_Wyqb[DD*DD];
__device__ unsigned short g_Wfkb[DD*CC], g_Wfvb[DD*CC];
__device__ unsigned short g_Qb[(size_t)NROW*CC];      // [row, 1024] = Q1|Q2
__device__ unsigned short g_Kb[(size_t)NROW*DD];
__device__ unsigned short g_Vtb[(size_t)BB*DD*SS];    // [b, d, s]
__device__ unsigned short g_Pb1[(size_t)BB*SS*SS];    // fp16 scores/probs (Q1)
__device__ unsigned short g_Pb2[(size_t)BB*SS*SS];    // fp16 scores/probs (Q2)

// ---------------------------------------------------------------------------
// Helpers
// ---------------------------------------------------------------------------
__device__ __forceinline__ uint32_t smem_u32(const void* p) {
    uint32_t a;
    asm("{ .reg .u64 t; cvta.to.shared.u64 t, %1; cvt.u32.u64 %0, t; }"
        : "=r"(a) : "l"(p));
    return a;
}
__device__ __forceinline__ void cp16(uint32_t s, const void* g) {
    asm volatile("cp.async.cg.shared.global [%0], [%1], 16;" :: "r"(s), "l"(g));
}
#define CP_COMMIT() asm volatile("cp.async.commit_group;" ::: "memory")
#define CP_WAIT0()  asm volatile("cp.async.wait_group 0;" ::: "memory")

__device__ __forceinline__ void ldm_x4(uint32_t* r, uint32_t a) {
    asm volatile("ldmatrix.sync.aligned.m8n8.x4.shared.b16 {%0,%1,%2,%3}, [%4];"
        : "=r"(r[0]), "=r"(r[1]), "=r"(r[2]), "=r"(r[3]) : "r"(a));
}
// fp16 MMA with fp16 accumulator: 2 acc regs (4 halves)
__device__ __forceinline__ void mma_f16(uint32_t* d, const uint32_t* a, const uint32_t* b) {
    asm volatile(
        "mma.sync.aligned.m16n8k16.row.col.f16.f16.f16.f16 "
        "{%0,%1}, {%2,%3,%4,%5}, {%6,%7}, {%0,%1};"
        : "+r"(d[0]), "+r"(d[1])
        : "r"(a[0]), "r"(a[1]), "r"(a[2]), "r"(a[3]), "r"(b[0]), "r"(b[1]));
}
__device__ __forceinline__ unsigned short f2h(float v) {
    return __half_as_ushort(__float2half_rn(v));
}
__device__ __forceinline__ float h2f(unsigned short v) {
    return __half2float(__ushort_as_half(v));
}

// ---------------------------------------------------------------------------
// SMEM: 2 stages x (A 128x64 | B 256x64) fp16, row stride 144B (conflict-free).
// 108KB per CTA -> two CTAs co-resident per SM.
// ---------------------------------------------------------------------------
#define STAGES     2
#define ROWB       144
#define A_TILE_B   (128 * ROWB)               // 18432
#define B_TILE_B   (256 * ROWB)               // 36864
#define STAGE_B    (A_TILE_B + B_TILE_B)      // 55296
#define SMEM_TOTAL (STAGES * STAGE_B)         // 110592

// ---------------------------------------------------------------------------
// Single-pass fp16 TN GEMM (fp16 acc), CTA tile 128(m) x 256(n), 256 thr
// (8 warps 2x4, warp tile 64x64), k-chunk 64, double-buffered, 2 CTAs/SM.
//
// z-split: if (blockIdx.z >= zsplit > 0) switch to the alt operand/output set.
// K-concat: A covers K via [Aseg1 (KA cols) | Aseg2]; B k-index wraps by bmask.
//
// mode 1: Ch[m*ld+n] = f16(acc + bias[n])
// mode 2: Ch[n*ld+m] = f16(acc + bias[n])   (transposed)
// mode 3: Cf[m*ld+n] = acc + add1? + add2?
// mode 5: Ch[m*ld+n] = f16(alpha*acc)
// ---------------------------------------------------------------------------
__global__ __launch_bounds__(256, 2) void hmma_tn(
    const unsigned short* __restrict__ A, const unsigned short* __restrict__ Aseg2,
    int KA, const unsigned short* __restrict__ B, int bmask,
    int K, int lda, int ldb, long long a_bs, long long b_bs,
    int zsplit,
    int mode, float alpha, const float* __restrict__ bias,
    float* __restrict__ Cf, unsigned short* __restrict__ Cb,
    long long c_bs, int c_ld,
    const float* __restrict__ add1, const float* __restrict__ add2,
    const unsigned short* __restrict__ A_alt, const unsigned short* __restrict__ B_alt,
    const float* __restrict__ bias_alt, unsigned short* __restrict__ Cb_alt,
    long long cbs_alt, int cld_alt, int mode_alt)
{
    extern __shared__ char smem[];
    const uint32_t sbase = smem_u32(smem);

    const int tid  = threadIdx.x;
    const int wid  = tid >> 5;
    const int lane = tid & 31;
    const int warpM = wid >> 2;      // 0..1 (64 rows each)
    const int warpN = wid & 3;       // 0..3 (64 cols each)
    int bz = blockIdx.z;
    const int bm = blockIdx.y * 128, bn = blockIdx.x * 256;

    // operand-set select
    const unsigned short* Ab = A;
    const unsigned short* Bb = B;
    const float* biasp = bias;
    unsigned short* Cbp = Cb;
    long long cbs = c_bs;
    int cld = c_ld;
    int md = mode;
    if (zsplit > 0 && bz >= zsplit) {
        bz -= zsplit;
        Ab = A_alt; Bb = B_alt; biasp = bias_alt;
        Cbp = Cb_alt; cbs = cbs_alt; cld = cld_alt; md = mode_alt;
    }

    const unsigned short* gA1 = Ab + bz * a_bs + (long long)bm * lda;
    const unsigned short* gA2 =
        Aseg2 ? Aseg2 + bz * a_bs + (long long)bm * lda : nullptr;
    const unsigned short* gB = Bb + bz * b_bs + (long long)bn * ldb;

    uint32_t acc[4][8][2];
#pragma unroll
    for (int i = 0; i < 4; ++i)
#pragma unroll
        for (int j = 0; j < 8; ++j) { acc[i][j][0] = 0u; acc[i][j][1] = 0u; }

    const int nch = K >> 6;   // k-chunks of 64

    const int lr = tid >> 3, lc = tid & 7;   // 32 rows x 8 segs per pass
#define LOAD_CHUNK(c)                                                        \
    do {                                                                     \
        const int koff_ = (c) * 64;                                          \
        const unsigned short* gAc_ = gA1; int ka_ = koff_;                   \
        if (gA2 && koff_ >= KA) { gAc_ = gA2; ka_ = koff_ - KA; }            \
        const int kb_ = koff_ & bmask;                                       \
        const uint32_t sb_ = sbase + ((c) & 1) * STAGE_B;                    \
        _Pragma("unroll")                                                    \
        for (int h_ = 0; h_ < 4; ++h_) {      /* A: 128 rows */              \
            const int row_ = lr + h_ * 32;                                   \
            cp16(sb_ + (uint32_t)(row_ * ROWB + lc * 16),                    \
                 gAc_ + (long long)row_ * lda + ka_ + lc * 8);               \
        }                                                                    \
        _Pragma("unroll")                                                    \
        for (int h_ = 0; h_ < 8; ++h_) {      /* B: 256 rows */              \
            const int row_ = lr + h_ * 32;                                   \
            cp16(sb_ + A_TILE_B + (uint32_t)(row_ * ROWB + lc * 16),         \
                 gB + (long long)row_ * ldb + kb_ + lc * 8);                 \
        }                                                                    \
        CP_COMMIT();                                                         \
    } while (0)

    LOAD_CHUNK(0);

    // ldmatrix geometry
    const int a_row = warpM * 64 + (lane & 15);
    const int a_colb = (lane >> 4) * 16;
    const int b_row = warpN * 64 + (lane & 7) + ((lane >> 4) & 1) * 8;
    const int b_colb = ((lane >> 3) & 1) * 16;

    for (int c = 0; c < nch; ++c) {
        CP_WAIT0();            // chunk c resident
        __syncthreads();       // all warps done reading buffer (c&1) from c-2

        // Prefetch chunk c+1 into the other buffer; overlaps compute below.
        if (c + 1 < nch) LOAD_CHUNK(c + 1);

        const uint32_t tA = sbase + (c & 1) * STAGE_B;
        const uint32_t tB = tA + A_TILE_B;

#pragma unroll
        for (int ks = 0; ks < 4; ++ks) {      // four k16 steps per chunk
            uint32_t af[4][4], bfr[8][2];
#pragma unroll
            for (int mi = 0; mi < 4; ++mi)
                ldm_x4(af[mi], tA + (uint32_t)((a_row + mi * 16) * ROWB
                                               + ks * 32 + a_colb));
#pragma unroll
            for (int p = 0; p < 4; ++p) {     // n16 pair -> two n8 frags
                uint32_t r[4];
                ldm_x4(r, tB + (uint32_t)((b_row + p * 16) * ROWB
                                          + ks * 32 + b_colb));
                bfr[2*p][0] = r[0]; bfr[2*p][1] = r[1];
                bfr[2*p+1][0] = r[2]; bfr[2*p+1][1] = r[3];
            }
#pragma unroll
            for (int mi = 0; mi < 4; ++mi)
#pragma unroll
                for (int ni = 0; ni < 8; ++ni)
                    mma_f16(acc[mi][ni], af[mi], bfr[ni]);
        }
    }
#undef LOAD_CHUNK

    // ------------------------- epilogue (register direct) -------------------
    const int g = lane >> 2, tig = lane & 3;
    const long long c_off = (long long)bz * cbs;

#pragma unroll
    for (int mi = 0; mi < 4; ++mi) {
#pragma unroll
        for (int ni = 0; ni < 8; ++ni) {
            const int m0 = bm + warpM * 64 + mi * 16 + g;
            const int n0 = bn + warpN * 64 + ni * 8 + tig * 2;
#pragma unroll
            for (int half = 0; half < 2; ++half) {
                const int m = m0 + half * 8;
                const __half2 hv = *(const __half2*)&acc[mi][ni][half];
                float v0 = __low2float(hv);
                float v1 = __high2float(hv);
                if (md == 5) {
                    *(ushort2*)&Cbp[c_off + (long long)m * cld + n0] =
                        make_ushort2(f2h(alpha * v0), f2h(alpha * v1));
                } else if (md == 1) {
                    v0 += __ldg(biasp + n0);
                    v1 += __ldg(biasp + n0 + 1);
                    *(ushort2*)&Cbp[c_off + (long long)m * cld + n0] =
                        make_ushort2(f2h(v0), f2h(v1));
                } else if (md == 2) {
                    v0 += __ldg(biasp + n0);
                    v1 += __ldg(biasp + n0 + 1);
                    Cbp[c_off + (long long)n0 * cld + m] = f2h(v0);
                    Cbp[c_off + (long long)(n0 + 1) * cld + m] = f2h(v1);
                } else {  // mode 3
                    const long long o = c_off + (long long)m * cld + n0;
                    if (add1) { float2 t = *(const float2*)&add1[o]; v0 += t.x; v1 += t.y; }
                    if (add2) { float2 t = *(const float2*)&add2[o]; v0 += t.x; v1 += t.y; }
                    *(float2*)&Cf[o] = make_float2(v0, v1);
                }
            }
        }
    }
}

// ---------------------------------------------------------------------------
// fp32 -> fp16, vectorized: float4 in, ushort4 (8B) out, 4 elems/thread.
// Two equal-size arrays in one launch; n must be a multiple of 4.
// ---------------------------------------------------------------------------
__global__ __launch_bounds__(256) void tofp16_dual(
    const float* __restrict__ s1, unsigned short* __restrict__ d1,
    const float* __restrict__ s2, unsigned short* __restrict__ d2, int n)
{
    const int q = n >> 2;   // float4 count per array
    const int i = blockIdx.x * 256 + threadIdx.x;
    const float* s;
    unsigned short* d;
    int j;
    if (i < q)           { s = s1; d = d1; j = i; }
    else if (i < 2 * q)  { s = s2; d = d2; j = i - q; }
    else return;
    const float4 v = *(const float4*)(s + (size_t)j * 4);
    ushort4 o;
    o.x = f2h(v.x); o.y = f2h(v.y); o.z = f2h(v.z); o.w = f2h(v.w);
    *(ushort4*)(d + (size_t)j * 4) = o;
}

// ---------------------------------------------------------------------------
// Row softmax (rows of 2048) in place over two buffers in one launch.
// Vectorized: each of 256 threads owns one uint4 = 8 CONTIGUOUS halves.
// ---------------------------------------------------------------------------
__global__ __launch_bounds__(256) void softmax_f16(
    unsigned short* __restrict__ P1, unsigned short* __restrict__ P2)
{
    unsigned short* Pb = (blockIdx.x < NROW) ? P1 : P2;
    const long long rb = (long long)(blockIdx.x & (NROW - 1)) * 2048;
    uint4* row = (uint4*)(Pb + rb);           // 256 x uint4 per row
    const int t = threadIdx.x;
    __shared__ float red[8];

    const uint4 pk = row[t];
    float v[8];
    {
        const __half2* h = (const __half2*)&pk;
#pragma unroll
        for (int i = 0; i < 4; ++i) {
            const float2 f = __half22float2(h[i]);
            v[2*i]   = f.x;
            v[2*i+1] = f.y;
        }
    }

    float mx = v[0];
#pragma unroll
    for (int i = 1; i < 8; ++i) mx = fmaxf(mx, v[i]);
#pragma unroll
    for (int o = 16; o > 0; o >>= 1) mx = fmaxf(mx, __shfl_xor_sync(0xffffffffu, mx, o));
    if ((t & 31) == 0) red[t >> 5] = mx;
    __syncthreads();
    mx = red[0];
#pragma unroll
    for (int w = 1; w < 8; ++w) mx = fmaxf(mx, red[w]);
    __syncthreads();

    float s = 0.f;
#pragma unroll
    for (int i = 0; i < 8; ++i) {
        v[i] = __expf(v[i] - mx);
        s += v[i];
    }
#pragma unroll
    for (int o = 16; o > 0; o >>= 1) s += __shfl_xor_sync(0xffffffffu, s, o);
    if ((t & 31) == 0) red[t >> 5] = s;
    __syncthreads();
    s = red[0];
#pragma unroll
    for (int w = 1; w < 8; ++w) s += red[w];

    const float inv = 1.0f / s;
    uint4 ok;
    {
        __half2* h = (__half2*)&ok;
#pragma unroll
        for (int i = 0; i < 4; ++i)
            h[i] = __floats2half2_rn(v[2*i] * inv, v[2*i+1] * inv);
    }
    row[t] = ok;
}

// ---------------------------------------------------------------------------
// Launch sequence
// ---------------------------------------------------------------------------
extern "C" void kernel_launch(void* const* d_in, const int* in_sizes, int n_in,
                              void* d_out, int out_size)
{
    (void)in_sizes; (void)n_in; (void)out_size;

    const float* X    = (const float*)d_in[0];
    const float* Y    = (const float*)d_in[1];
    const float* W_xq = (const float*)d_in[2];
    const float* b_xq = (const float*)d_in[3];
    const float* W_yq = (const float*)d_in[4];
    const float* b_yq = (const float*)d_in[5];
    const float* W_fk = (const float*)d_in[6];
    const float* b_fk = (const float*)d_in[7];
    const float* W_fv = (const float*)d_in[8];
    const float* b_fv = (const float*)d_in[9];
    float* out = (float*)d_out;

#define SYM(T, name, gsym) T* name; cudaGetSymbolAddress((void**)&name, gsym)
    SYM(unsigned short, Xb, g_Xb);     SYM(unsigned short, Yb, g_Yb);
    SYM(unsigned short, Wxqb, g_Wxqb); SYM(unsigned short, Wyqb, g_Wyqb);
    SYM(unsigned short, Wfkb, g_Wfkb); SYM(unsigned short, Wfvb, g_Wfvb);
    SYM(unsigned short, Qb, g_Qb);     SYM(unsigned short, Kb, g_Kb);
    SYM(unsigned short, Vtb, g_Vtb);
    SYM(unsigned short, Pb1, g_Pb1);   SYM(unsigned short, Pb2, g_Pb2);
#undef SYM

    cudaFuncSetAttribute(hmma_tn, cudaFuncAttributeMaxDynamicSharedMemorySize, SMEM_TOTAL);

    const float scale = 0.04419417382415922f;  // 1/sqrt(512)
    const long long XBS = (long long)SS * DD;
    const long long QBS = (long long)SS * CC;
    const long long PBS = (long long)SS * SS;
    const long long VBS = (long long)DD * SS;

    // ---- fp16 conversions (vectorized: 4 elems/thread) ----
    const int nX = NROW * DD;
    tofp16_dual<<<(2 * (nX / 4)) / 256, 256>>>(X, Xb, Y, Yb, nX);
    tofp16_dual<<<(2 * (DD * DD / 4)) / 256, 256>>>(W_xq, Wxqb, W_yq, Wyqb, DD * DD);
    tofp16_dual<<<(2 * (DD * CC / 4)) / 256, 256>>>(W_fk, Wfkb, W_fv, Wfvb, DD * CC);

    // ---- projections: Q1 (z<8) and Q2 (z>=8) in one launch ----
    hmma_tn<<<dim3(2, 16, 16), 256, SMEM_TOTAL>>>(
        Xb, nullptr, DD, Wxqb, DD - 1,
        DD, DD, DD, XBS, 0, /*zsplit*/8,
        1, 1.f, b_xq, nullptr, Qb, QBS, CC, nullptr, nullptr,
        Yb, Wyqb, b_yq, Qb + DD, QBS, CC, 1);

    // ---- Kf (z<8, mode 1) and Vt (z>=8, mode 2 transposed) ----
    hmma_tn<<<dim3(2, 16, 16), 256, SMEM_TOTAL>>>(
        Qb, nullptr, CC, Wfkb, CC - 1,
        CC, CC, CC, QBS, 0, /*zsplit*/8,
        1, 1.f, b_fk, nullptr, Kb, XBS, DD, nullptr, nullptr,
        Qb, Wfvb, b_fv, Vtb, VBS, SS, 2);

    // ---- QK: scores for Q1 -> Pb1 (z<8) and Q2 -> Pb2 (z>=8) ----
    hmma_tn<<<dim3(8, 16, 16), 256, SMEM_TOTAL>>>(
        Qb, nullptr, DD, Kb, DD - 1,
        DD, CC, DD, QBS, XBS, /*zsplit*/8,
        5, scale, nullptr, nullptr, Pb1, PBS, SS, nullptr, nullptr,
        Qb + DD, Kb, nullptr, Pb2, PBS, SS, 5);

    // ---- softmax over both buffers (coalesced uint4 path) ----
    softmax_f16<<<2 * NROW, 256>>>(Pb1, Pb2);

    // ---- fused PV: out = P1@Vt^T + P2@Vt^T + X + Y  (K = 4096 concat) ----
    hmma_tn<<<dim3(2, 16, 8), 256, SMEM_TOTAL>>>(
        Pb1, Pb2, SS, Vtb, SS - 1,
        2 * SS, SS, SS, PBS, VBS, /*zsplit*/0,
        3, 1.f, nullptr, out, nullptr, XBS, DD, X, Y,
        nullptr, nullptr, nullptr, nullptr, 0, 0, 0);
}

// round 15
// speedup vs baseline: 1.2327x; 1.0215x over previous
#include <cuda_runtime.h>
#include <cuda_fp16.h>
#include <cstdint>

#define BB 8
#define SS 2048
#define DD 512
#define CC 1024
#define NROW (BB*SS)   // 16384

// ---------------------------------------------------------------------------
// Scratch (device globals), fp16 as ushort
// ---------------------------------------------------------------------------
__device__ unsigned short g_Xb[(size_t)NROW*DD], g_Yb[(size_t)NROW*DD];
__device__ unsigned short g_Wxqb[DD*DD], g_Wyqb[DD*DD];
__device__ unsigned short g_Wfkb[DD*CC], g_Wfvb[DD*CC];
__device__ unsigned short g_Qb[(size_t)NROW*CC];      // [row, 1024] = Q1|Q2
__device__ unsigned short g_Kb[(size_t)NROW*DD];
__device__ unsigned short g_Vtb[(size_t)BB*DD*SS];    // [b, d, s]
__device__ unsigned short g_Pb1[(size_t)BB*SS*SS];    // fp16 scores/probs (Q1)
__device__ unsigned short g_Pb2[(size_t)BB*SS*SS];    // fp16 scores/probs (Q2)

// ---------------------------------------------------------------------------
// Helpers
// ---------------------------------------------------------------------------
__device__ __forceinline__ uint32_t smem_u32(const void* p) {
    uint32_t a;
    asm("{ .reg .u64 t; cvta.to.shared.u64 t, %1; cvt.u32.u64 %0, t; }"
        : "=r"(a) : "l"(p));
    return a;
}
__device__ __forceinline__ void cp16(uint32_t s, const void* g) {
    asm volatile("cp.async.cg.shared.global [%0], [%1], 16;" :: "r"(s), "l"(g));
}
#define CP_COMMIT() asm volatile("cp.async.commit_group;" ::: "memory")
#define CP_WAIT0()  asm volatile("cp.async.wait_group 0;" ::: "memory")

__device__ __forceinline__ void ldm_x4(uint32_t* r, uint32_t a) {
    asm volatile("ldmatrix.sync.aligned.m8n8.x4.shared.b16 {%0,%1,%2,%3}, [%4];"
        : "=r"(r[0]), "=r"(r[1]), "=r"(r[2]), "=r"(r[3]) : "r"(a));
}
// fp16 MMA with fp16 accumulator: 2 acc regs (4 halves)
__device__ __forceinline__ void mma_f16(uint32_t* d, const uint32_t* a, const uint32_t* b) {
    asm volatile(
        "mma.sync.aligned.m16n8k16.row.col.f16.f16.f16.f16 "
        "{%0,%1}, {%2,%3,%4,%5}, {%6,%7}, {%0,%1};"
        : "+r"(d[0]), "+r"(d[1])
        : "r"(a[0]), "r"(a[1]), "r"(a[2]), "r"(a[3]), "r"(b[0]), "r"(b[1]));
}
__device__ __forceinline__ unsigned short f2h(float v) {
    return __half_as_ushort(__float2half_rn(v));
}

// ---------------------------------------------------------------------------
// SMEM: 2 stages x (A 128x64 | B 128x64) fp16, row stride 144B (conflict-free).
// 72KB per CTA -> THREE CTAs co-resident per SM (221KB <= 227KB).
// ---------------------------------------------------------------------------
#define STAGES     2
#define ROWB       144
#define A_TILE_B   (128 * ROWB)               // 18432
#define B_TILE_B   (128 * ROWB)               // 18432
#define STAGE_B    (A_TILE_B + B_TILE_B)      // 36864
#define SMEM_TOTAL (STAGES * STAGE_B)         // 73728

// ---------------------------------------------------------------------------
// Single-pass fp16 TN GEMM (fp16 acc), CTA tile 128(m) x 128(n), 256 thr
// (8 warps 2x4, warp tile 64x32, ~80 regs), k-chunk 64, double-buffered,
// 3 CTAs/SM (24 warps/SM) for latency hiding.
//
// z-split: if (blockIdx.z >= zsplit > 0) switch to the alt operand/output set.
// K-concat: A covers K via [Aseg1 (KA cols) | Aseg2]; B k-index wraps by bmask.
//
// mode 1: Ch[m*ld+n] = f16(acc + bias[n])
// mode 2: Ch[n*ld+m] = f16(acc + bias[n])   (transposed)
// mode 3: Cf[m*ld+n] = acc + add1? + add2?
// mode 5: Ch[m*ld+n] = f16(alpha*acc)
// ---------------------------------------------------------------------------
__global__ __launch_bounds__(256, 3) void hmma_tn(
    const unsigned short* __restrict__ A, const unsigned short* __restrict__ Aseg2,
    int KA, const unsigned short* __restrict__ B, int bmask,
    int K, int lda, int ldb, long long a_bs, long long b_bs,
    int zsplit,
    int mode, float alpha, const float* __restrict__ bias,
    float* __restrict__ Cf, unsigned short* __restrict__ Cb,
    long long c_bs, int c_ld,
    const float* __restrict__ add1, const float* __restrict__ add2,
    const unsigned short* __restrict__ A_alt, const unsigned short* __restrict__ B_alt,
    const float* __restrict__ bias_alt, unsigned short* __restrict__ Cb_alt,
    long long cbs_alt, int cld_alt, int mode_alt)
{
    extern __shared__ char smem[];
    const uint32_t sbase = smem_u32(smem);

    const int tid  = threadIdx.x;
    const int wid  = tid >> 5;
    const int lane = tid & 31;
    const int warpM = wid >> 2;      // 0..1 (64 rows each)
    const int warpN = wid & 3;       // 0..3 (32 cols each)
    int bz = blockIdx.z;
    const int bm = blockIdx.y * 128, bn = blockIdx.x * 128;

    // operand-set select
    const unsigned short* Ab = A;
    const unsigned short* Bb = B;
    const float* biasp = bias;
    unsigned short* Cbp = Cb;
    long long cbs = c_bs;
    int cld = c_ld;
    int md = mode;
    if (zsplit > 0 && bz >= zsplit) {
        bz -= zsplit;
        Ab = A_alt; Bb = B_alt; biasp = bias_alt;
        Cbp = Cb_alt; cbs = cbs_alt; cld = cld_alt; md = mode_alt;
    }

    const unsigned short* gA1 = Ab + bz * a_bs + (long long)bm * lda;
    const unsigned short* gA2 =
        Aseg2 ? Aseg2 + bz * a_bs + (long long)bm * lda : nullptr;
    const unsigned short* gB = Bb + bz * b_bs + (long long)bn * ldb;

    uint32_t acc[4][4][2];
#pragma unroll
    for (int i = 0; i < 4; ++i)
#pragma unroll
        for (int j = 0; j < 4; ++j) { acc[i][j][0] = 0u; acc[i][j][1] = 0u; }

    const int nch = K >> 6;   // k-chunks of 64

    const int lr = tid >> 3, lc = tid & 7;   // 32 rows x 8 segs per pass
#define LOAD_CHUNK(c)                                                        \
    do {                                                                     \
        const int koff_ = (c) * 64;                                          \
        const unsigned short* gAc_ = gA1; int ka_ = koff_;                   \
        if (gA2 && koff_ >= KA) { gAc_ = gA2; ka_ = koff_ - KA; }            \
        const int kb_ = koff_ & bmask;                                       \
        const uint32_t sb_ = sbase + ((c) & 1) * STAGE_B;                    \
        _Pragma("unroll")                                                    \
        for (int h_ = 0; h_ < 4; ++h_) {      /* A: 128 rows */              \
            const int row_ = lr + h_ * 32;                                   \
            cp16(sb_ + (uint32_t)(row_ * ROWB + lc * 16),                    \
                 gAc_ + (long long)row_ * lda + ka_ + lc * 8);               \
        }                                                                    \
        _Pragma("unroll")                                                    \
        for (int h_ = 0; h_ < 4; ++h_) {      /* B: 128 rows */              \
            const int row_ = lr + h_ * 32;                                   \
            cp16(sb_ + A_TILE_B + (uint32_t)(row_ * ROWB + lc * 16),         \
                 gB + (long long)row_ * ldb + kb_ + lc * 8);                 \
        }                                                                    \
        CP_COMMIT();                                                         \
    } while (0)

    LOAD_CHUNK(0);

    // ldmatrix geometry
    const int a_row = warpM * 64 + (lane & 15);
    const int a_colb = (lane >> 4) * 16;
    const int b_row = warpN * 32 + (lane & 7) + ((lane >> 4) & 1) * 8;
    const int b_colb = ((lane >> 3) & 1) * 16;

    for (int c = 0; c < nch; ++c) {
        CP_WAIT0();            // chunk c resident
        __syncthreads();       // all warps done reading buffer (c&1) from c-2

        // Prefetch chunk c+1 into the other buffer; overlaps compute below.
        if (c + 1 < nch) LOAD_CHUNK(c + 1);

        const uint32_t tA = sbase + (c & 1) * STAGE_B;
        const uint32_t tB = tA + A_TILE_B;

#pragma unroll
        for (int ks = 0; ks < 4; ++ks) {      // four k16 steps per chunk
            uint32_t af[4][4], bfr[4][2];
#pragma unroll
            for (int mi = 0; mi < 4; ++mi)
                ldm_x4(af[mi], tA + (uint32_t)((a_row + mi * 16) * ROWB
                                               + ks * 32 + a_colb));
#pragma unroll
            for (int p = 0; p < 2; ++p) {     // n16 pair -> two n8 frags
                uint32_t r[4];
                ldm_x4(r, tB + (uint32_t)((b_row + p * 16) * ROWB
                                          + ks * 32 + b_colb));
                bfr[2*p][0] = r[0]; bfr[2*p][1] = r[1];
                bfr[2*p+1][0] = r[2]; bfr[2*p+1][1] = r[3];
            }
#pragma unroll
            for (int mi = 0; mi < 4; ++mi)
#pragma unroll
                for (int ni = 0; ni < 4; ++ni)
                    mma_f16(acc[mi][ni], af[mi], bfr[ni]);
        }
    }
#undef LOAD_CHUNK

    // ------------------------- epilogue (register direct) -------------------
    const int g = lane >> 2, tig = lane & 3;
    const long long c_off = (long long)bz * cbs;

#pragma unroll
    for (int mi = 0; mi < 4; ++mi) {
#pragma unroll
        for (int ni = 0; ni < 4; ++ni) {
            const int m0 = bm + warpM * 64 + mi * 16 + g;
            const int n0 = bn + warpN * 32 + ni * 8 + tig * 2;
#pragma unroll
            for (int half = 0; half < 2; ++half) {
                const int m = m0 + half * 8;
                const __half2 hv = *(const __half2*)&acc[mi][ni][half];
                float v0 = __low2float(hv);
                float v1 = __high2float(hv);
                if (md == 5) {
                    *(ushort2*)&Cbp[c_off + (long long)m * cld + n0] =
                        make_ushort2(f2h(alpha * v0), f2h(alpha * v1));
                } else if (md == 1) {
                    v0 += __ldg(biasp + n0);
                    v1 += __ldg(biasp + n0 + 1);
                    *(ushort2*)&Cbp[c_off + (long long)m * cld + n0] =
                        make_ushort2(f2h(v0), f2h(v1));
                } else if (md == 2) {
                    v0 += __ldg(biasp + n0);
                    v1 += __ldg(biasp + n0 + 1);
                    Cbp[c_off + (long long)n0 * cld + m] = f2h(v0);
                    Cbp[c_off + (long long)(n0 + 1) * cld + m] = f2h(v1);
                } else {  // mode 3
                    const long long o = c_off + (long long)m * cld + n0;
                    if (add1) { float2 t = *(const float2*)&add1[o]; v0 += t.x; v1 += t.y; }
                    if (add2) { float2 t = *(const float2*)&add2[o]; v0 += t.x; v1 += t.y; }
                    *(float2*)&Cf[o] = make_float2(v0, v1);
                }
            }
        }
    }
}

// ---------------------------------------------------------------------------
// fp32 -> fp16, vectorized: float4 in, ushort4 (8B) out, 4 elems/thread.
// Two equal-size arrays in one launch; n must be a multiple of 4.
// ---------------------------------------------------------------------------
__global__ __launch_bounds__(256) void tofp16_dual(
    const float* __restrict__ s1, unsigned short* __restrict__ d1,
    const float* __restrict__ s2, unsigned short* __restrict__ d2, int n)
{
    const int q = n >> 2;   // float4 count per array
    const int i = blockIdx.x * 256 + threadIdx.x;
    const float* s;
    unsigned short* d;
    int j;
    if (i < q)           { s = s1; d = d1; j = i; }
    else if (i < 2 * q)  { s = s2; d = d2; j = i - q; }
    else return;
    const float4 v = *(const float4*)(s + (size_t)j * 4);
    ushort4 o;
    o.x = f2h(v.x); o.y = f2h(v.y); o.z = f2h(v.z); o.w = f2h(v.w);
    *(ushort4*)(d + (size_t)j * 4) = o;
}

// ---------------------------------------------------------------------------
// Row softmax (rows of 2048) in place over two buffers in one launch.
// Vectorized: each of 256 threads owns one uint4 = 8 CONTIGUOUS halves.
// ---------------------------------------------------------------------------
__global__ __launch_bounds__(256) void softmax_f16(
    unsigned short* __restrict__ P1, unsigned short* __restrict__ P2)
{
    unsigned short* Pb = (blockIdx.x < NROW) ? P1 : P2;
    const long long rb = (long long)(blockIdx.x & (NROW - 1)) * 2048;
    uint4* row = (uint4*)(Pb + rb);           // 256 x uint4 per row
    const int t = threadIdx.x;
    __shared__ float red[8];

    const uint4 pk = row[t];
    float v[8];
    {
        const __half2* h = (const __half2*)&pk;
#pragma unroll
        for (int i = 0; i < 4; ++i) {
            const float2 f = __half22float2(h[i]);
            v[2*i]   = f.x;
            v[2*i+1] = f.y;
        }
    }

    float mx = v[0];
#pragma unroll
    for (int i = 1; i < 8; ++i) mx = fmaxf(mx, v[i]);
#pragma unroll
    for (int o = 16; o > 0; o >>= 1) mx = fmaxf(mx, __shfl_xor_sync(0xffffffffu, mx, o));
    if ((t & 31) == 0) red[t >> 5] = mx;
    __syncthreads();
    mx = red[0];
#pragma unroll
    for (int w = 1; w < 8; ++w) mx = fmaxf(mx, red[w]);
    __syncthreads();

    float s = 0.f;
#pragma unroll
    for (int i = 0; i < 8; ++i) {
        v[i] = __expf(v[i] - mx);
        s += v[i];
    }
#pragma unroll
    for (int o = 16; o > 0; o >>= 1) s += __shfl_xor_sync(0xffffffffu, s, o);
    if ((t & 31) == 0) red[t >> 5] = s;
    __syncthreads();
    s = red[0];
#pragma unroll
    for (int w = 1; w < 8; ++w) s += red[w];

    const float inv = 1.0f / s;
    uint4 ok;
    {
        __half2* h = (__half2*)&ok;
#pragma unroll
        for (int i = 0; i < 4; ++i)
            h[i] = __floats2half2_rn(v[2*i] * inv, v[2*i+1] * inv);
    }
    row[t] = ok;
}

// ---------------------------------------------------------------------------
// Launch sequence
// ---------------------------------------------------------------------------
extern "C" void kernel_launch(void* const* d_in, const int* in_sizes, int n_in,
                              void* d_out, int out_size)
{
    (void)in_sizes; (void)n_in; (void)out_size;

    const float* X    = (const float*)d_in[0];
    const float* Y    = (const float*)d_in[1];
    const float* W_xq = (const float*)d_in[2];
    const float* b_xq = (const float*)d_in[3];
    const float* W_yq = (const float*)d_in[4];
    const float* b_yq = (const float*)d_in[5];
    const float* W_fk = (const float*)d_in[6];
    const float* b_fk = (const float*)d_in[7];
    const float* W_fv = (const float*)d_in[8];
    const float* b_fv = (const float*)d_in[9];
    float* out = (float*)d_out;

#define SYM(T, name, gsym) T* name; cudaGetSymbolAddress((void**)&name, gsym)
    SYM(unsigned short, Xb, g_Xb);     SYM(unsigned short, Yb, g_Yb);
    SYM(unsigned short, Wxqb, g_Wxqb); SYM(unsigned short, Wyqb, g_Wyqb);
    SYM(unsigned short, Wfkb, g_Wfkb); SYM(unsigned short, Wfvb, g_Wfvb);
    SYM(unsigned short, Qb, g_Qb);     SYM(unsigned short, Kb, g_Kb);
    SYM(unsigned short, Vtb, g_Vtb);
    SYM(unsigned short, Pb1, g_Pb1);   SYM(unsigned short, Pb2, g_Pb2);
#undef SYM

    cudaFuncSetAttribute(hmma_tn, cudaFuncAttributeMaxDynamicSharedMemorySize, SMEM_TOTAL);

    const float scale = 0.04419417382415922f;  // 1/sqrt(512)
    const long long XBS = (long long)SS * DD;
    const long long QBS = (long long)SS * CC;
    const long long PBS = (long long)SS * SS;
    const long long VBS = (long long)DD * SS;

    // ---- fp16 conversions (vectorized: 4 elems/thread) ----
    const int nX = NROW * DD;
    tofp16_dual<<<(2 * (nX / 4)) / 256, 256>>>(X, Xb, Y, Yb, nX);
    tofp16_dual<<<(2 * (DD * DD / 4)) / 256, 256>>>(W_xq, Wxqb, W_yq, Wyqb, DD * DD);
    tofp16_dual<<<(2 * (DD * CC / 4)) / 256, 256>>>(W_fk, Wfkb, W_fv, Wfvb, DD * CC);

    // ---- projections: Q1 (z<8) and Q2 (z>=8) in one launch ----
    hmma_tn<<<dim3(4, 16, 16), 256, SMEM_TOTAL>>>(
        Xb, nullptr, DD, Wxqb, DD - 1,
        DD, DD, DD, XBS, 0, /*zsplit*/8,
        1, 1.f, b_xq, nullptr, Qb, QBS, CC, nullptr, nullptr,
        Yb, Wyqb, b_yq, Qb + DD, QBS, CC, 1);

    // ---- Kf (z<8, mode 1) and Vt (z>=8, mode 2 transposed) ----
    hmma_tn<<<dim3(4, 16, 16), 256, SMEM_TOTAL>>>(
        Qb, nullptr, CC, Wfkb, CC - 1,
        CC, CC, CC, QBS, 0, /*zsplit*/8,
        1, 1.f, b_fk, nullptr, Kb, XBS, DD, nullptr, nullptr,
        Qb, Wfvb, b_fv, Vtb, VBS, SS, 2);

    // ---- QK: scores for Q1 -> Pb1 (z<8) and Q2 -> Pb2 (z>=8) ----
    hmma_tn<<<dim3(16, 16, 16), 256, SMEM_TOTAL>>>(
        Qb, nullptr, DD, Kb, DD - 1,
        DD, CC, DD, QBS, XBS, /*zsplit*/8,
        5, scale, nullptr, nullptr, Pb1, PBS, SS, nullptr, nullptr,
        Qb + DD, Kb, nullptr, Pb2, PBS, SS, 5);

    // ---- softmax over both buffers (coalesced uint4 path) ----
    softmax_f16<<<2 * NROW, 256>>>(Pb1, Pb2);

    // ---- fused PV: out = P1@Vt^T + P2@Vt^T + X + Y  (K = 4096 concat) ----
    hmma_tn<<<dim3(4, 16, 8), 256, SMEM_TOTAL>>>(
        Pb1, Pb2, SS, Vtb, SS - 1,
        2 * SS, SS, SS, PBS, VBS, /*zsplit*/0,
        3, 1.f, nullptr, out, nullptr, XBS, DD, X, Y,
        nullptr, nullptr, nullptr, nullptr, 0, 0, 0);
}